// round 5
// baseline (speedup 1.0000x reference)
#include <cuda_runtime.h>
#include <math.h>

#define N_NODESC 20000
#define N_EDGESC 120000

// ---- static device scratch ----
__device__ int   g_deg[N_NODESC];
__device__ int   g_off[N_NODESC + 1];
__device__ int   g_cursor[N_NODESC];
__device__ int2  g_edge[N_EDGESC];                // sorted (src,dst)
__device__ float g_MW[16 * 384];                  // MW[p][t], t=j*24+u
__device__ float g_R[(size_t)N_NODESC * 384];     // R[n][j*24+u]
__device__ float g_T[(size_t)N_NODESC * 384];     // T[n][t'], t'=u*16+j

#define C_EMB   8.4335730690754870f     // 1.14136 * e^2
#define C_V     0.05103103630798287f    // 1/(4*sqrt(24))
#define C_LOGIT 0.003189439769248930f   // 1/(64*sqrt(24))

__device__ __forceinline__ float susf(float v) {
    return (v > 0.f) ? __expf(-__fdividef(1.f, v)) : 0.f;
}
__device__ __forceinline__ float siluf(float z) {
    return __fdividef(z, 1.f + __expf(-z));
}

// ---------------- block 0: MW = (0.25*C_LOGIT * Wq@Wdot) @ Wk2'' ; blocks>=1: zero deg ----------------
__global__ void k_zeroprep(const float* __restrict__ Wq,
                           const float* __restrict__ Wdot,
                           const float* __restrict__ Wk2) {
    int t = threadIdx.x;  // 384
    if (blockIdx.x == 0) {
        __shared__ float M[16][17];
        if (t < 256) {
            int p = t >> 4, w = t & 15;
            float a = 0.f;
            #pragma unroll
            for (int r = 0; r < 16; r++) a += __ldg(&Wq[p * 16 + r]) * __ldg(&Wdot[r * 16 + w]);
            M[p][w] = a * 0.25f * C_LOGIT;
        }
        __syncthreads();
        int j = t / 24;
        int u = t - j * 24;
        float wk[16];
        #pragma unroll
        for (int w = 0; w < 16; w++) wk[w] = __ldg(&Wk2[j * 384 + u * 16 + w]);
        #pragma unroll
        for (int p = 0; p < 16; p++) {
            float a = 0.f;
            #pragma unroll
            for (int w = 0; w < 16; w++) a += M[p][w] * wk[w];
            g_MW[p * 384 + t] = a;
        }
    } else {
        int i = (blockIdx.x - 1) * 384 + t;
        if (i < N_NODESC) g_deg[i] = 0;
    }
}

__global__ void k_hist(const int* __restrict__ dst) {
    int i = blockIdx.x * blockDim.x + threadIdx.x;
    if (i < N_EDGESC) atomicAdd(&g_deg[dst[i]], 1);
}

__global__ void k_scan() {
    __shared__ int s[1024];
    int tid = threadIdx.x;
    const int CH = (N_NODESC + 1023) / 1024;  // 20
    int base = tid * CH;
    int sum = 0;
    #pragma unroll
    for (int c = 0; c < CH; c++) {
        int idx = base + c;
        if (idx < N_NODESC) sum += g_deg[idx];
    }
    s[tid] = sum;
    __syncthreads();
    for (int d = 1; d < 1024; d <<= 1) {
        int v = (tid >= d) ? s[tid - d] : 0;
        __syncthreads();
        s[tid] += v;
        __syncthreads();
    }
    int run = s[tid] - sum;
    for (int c = 0; c < CH; c++) {
        int idx = base + c;
        if (idx < N_NODESC) {
            g_off[idx] = run;
            g_cursor[idx] = run;
            run += g_deg[idx];
        }
    }
    if (tid == 1023) g_off[N_NODESC] = s[1023];
}

__global__ void k_scatter(const int* __restrict__ src, const int* __restrict__ dst) {
    int i = blockIdx.x * blockDim.x + threadIdx.x;
    if (i < N_EDGESC) {
        int d = dst[i];
        int p = atomicAdd(&g_cursor[d], 1);
        g_edge[p] = make_int2(src[i], d);
    }
}

// ---------------- R GEMM: R[n][t] = sum_p x0[n][p] * MW[p][t] ----------------
#define RT_NODES 50
__global__ void k_R(const float* __restrict__ x) {
    __shared__ float sW[16][385];
    __shared__ float sq[RT_NODES * 16];
    int t = threadIdx.x;  // 0..383

    #pragma unroll
    for (int p = 0; p < 16; p++) sW[p][t] = g_MW[p * 384 + t];

    int nb = blockIdx.x * RT_NODES;
    for (int i = t; i < RT_NODES * 16; i += 384) {
        int n = i >> 4, c = i & 15;
        sq[i] = x[(size_t)(nb + n) * 40 + c];
    }
    __syncthreads();

    float wr[16];
    #pragma unroll
    for (int p = 0; p < 16; p++) wr[p] = sW[p][t];

    float* Rp = g_R + (size_t)nb * 384 + t;
    #pragma unroll 2
    for (int n0 = 0; n0 < RT_NODES; n0++) {
        const float4* q4 = (const float4*)(sq + n0 * 16);
        float4 qa = q4[0], qb = q4[1], qc = q4[2], qdv = q4[3];
        float a = wr[0] * qa.x + wr[1] * qa.y + wr[2] * qa.z + wr[3] * qa.w
                + wr[4] * qb.x + wr[5] * qb.y + wr[6] * qb.z + wr[7] * qb.w
                + wr[8] * qc.x + wr[9] * qc.y + wr[10] * qc.z + wr[11] * qc.w
                + wr[12] * qdv.x + wr[13] * qdv.y + wr[14] * qdv.z + wr[15] * qdv.w;
        Rp[(size_t)n0 * 384] = a;
    }
}

// ---------------- fused edge pass: warp per node ----------------
// R layout: t = j*24+u (j=t/24, u=t%24). T layout: t' = u*16+j = l+32k (j=l&15, u=(l>>4)+2k).
__global__ void k_edge(const float* __restrict__ x, const float* __restrict__ pos,
                       const float* __restrict__ Wk1, const float* __restrict__ Wv1) {
    __shared__ float sW[320];   // [0:160) Wk1, [160:320) Wv1
    int tid = threadIdx.x;
    int l = tid & 31, w = tid >> 5;
    for (int i = tid; i < 160; i += blockDim.x) {
        sW[i] = __ldg(&Wk1[i]);
        sW[160 + i] = __ldg(&Wv1[i]);
    }
    __syncthreads();

    int n = blockIdx.x * 8 + w;
    if (n >= N_NODESC) return;
    int beg = g_off[n], end = g_off[n + 1];

    float acc[12];
    #pragma unroll
    for (int k = 0; k < 12; k++) acc[k] = 0.f;
    float z = 0.f;

    if (beg < end) {
        // R row into registers (coalesced)
        float Rreg[12];
        const float* Rp = g_R + (size_t)n * 384;
        #pragma unroll
        for (int k = 0; k < 12; k++) Rreg[k] = Rp[l + 32 * k];

        // per-lane constant indices
        int jdx[12], udx[12], uacc[12];
        #pragma unroll
        for (int k = 0; k < 12; k++) {
            int t = l + 32 * k;
            jdx[k] = t / 24;
            udx[k] = t - jdx[k] * 24;
            uacc[k] = (l >> 4) + 2 * k;
        }
        int jj = l & 15;
        int m = l - 16;              // meaningful for lanes 16..23
        int i0 = 16 + 3 * m;
        int i1 = i0 + 1, i2x = i0 + 2;
        int swbase = (l < 16) ? 0 : 160;

        float pd0 = pos[n * 3 + 0], pd1 = pos[n * 3 + 1], pd2 = pos[n * 3 + 2];

        for (int i = beg; i < end; i++) {
            int s = g_edge[i].x;
            float ev0 = pos[s * 3 + 0] - pd0;
            float ev1 = pos[s * 3 + 1] - pd1;
            float ev2 = pos[s * 3 + 2] - pd2;
            float elen = sqrtf(ev0 * ev0 + ev1 * ev1 + ev2 * ev2 + 1e-12f);
            float wcut = susf(10.f * (1.f - elen * 0.25f));
            if (!(wcut > 0.f)) continue;     // warp-uniform

            float tt = elen * 2.75f;
            int b0 = (int)tt;
            float d0 = tt - (float)b0;
            float g0 = (b0 >= 1 && b0 <= 10) ? (C_EMB * susf(d0 + 1.f) * susf(1.f - d0)) : 0.f;
            float g1 = (b0 >= 0 && b0 <= 9)  ? (C_EMB * susf(d0) * susf(2.f - d0)) : 0.f;
            int r0 = b0 - 1; if (r0 < 0) r0 = 0; if (r0 > 9) r0 = 9;
            int r1 = b0;     if (r1 < 0) r1 = 0; if (r1 > 9) r1 = 9;

            // x[src] row distributed across lanes
            float A = x[(size_t)s * 40 + l];
            float B = (l < 8) ? x[(size_t)s * 40 + 32 + l] : 0.f;

            // Y: lanes 0..15 = x0, lanes 16..23 = x1dot
            float a0 = __shfl_sync(0xffffffffu, A, i0 & 31);
            float b0s = __shfl_sync(0xffffffffu, B, (i0 - 32) & 31);
            float a1 = __shfl_sync(0xffffffffu, A, i1 & 31);
            float b1s = __shfl_sync(0xffffffffu, B, (i1 - 32) & 31);
            float a2 = __shfl_sync(0xffffffffu, A, i2x & 31);
            float b2s = __shfl_sync(0xffffffffu, B, (i2x - 32) & 31);
            float v0 = (i0 < 32) ? a0 : b0s;
            float v1 = (i1 < 32) ? a1 : b1s;
            float v2 = (i2x < 32) ? a2 : b2s;
            float rinv = __frcp_rn(elen);
            float Y;
            if (l < 16)      Y = A;
            else if (l < 24) Y = (v0 * ev0 + v1 * ev1 + v2 * ev2) * rinv;
            else             Y = 0.f;

            // H: lanes 0..15 hk, 16..31 hv (one silu per lane)
            float wv0 = sW[swbase + r0 * 16 + jj];
            float wv1 = sW[swbase + r1 * 16 + jj];
            float H = siluf(g0 * wv0 + g1 * wv1);

            // logit = sum_t R[t]*hk[j(t)]*y[u(t)], distributed
            float lp = 0.f;
            #pragma unroll
            for (int k = 0; k < 12; k++) {
                float hkv = __shfl_sync(0xffffffffu, H, jdx[k]);
                float yv  = __shfl_sync(0xffffffffu, Y, udx[k]);
                lp += Rreg[k] * hkv * yv;
            }
            #pragma unroll
            for (int o = 16; o > 0; o >>= 1)
                lp += __shfl_xor_sync(0xffffffffu, lp, o);

            float expv = wcut * __expf(lp);
            z += expv;
            float sh = sqrtf(expv) * __shfl_sync(0xffffffffu, H, 16 + jj);
            #pragma unroll
            for (int k = 0; k < 12; k++) {
                float yv = __shfl_sync(0xffffffffu, Y, uacc[k]);
                acc[k] += sh * yv;
            }
        }
    }

    if (z == 0.f) z = 1.f;
    float sc = rsqrtf(z);
    float* Tp = g_T + (size_t)n * 384;
    #pragma unroll
    for (int k = 0; k < 12; k++) Tp[l + 32 * k] = acc[k] * sc;
}

// ---------------- output GEMM: out = C_V * T @ W', float4 inner ----------------
__global__ void k_out(const float* __restrict__ Wv2, float* __restrict__ out) {
    __shared__ __align__(16) float sW[32][36];
    __shared__ __align__(16) float sT[128][36];
    int t = threadIdx.x;                // 256
    int base = blockIdx.x * 128;
    int c0 = t & 15;
    int g = t >> 4;

    float acc[8][2];
    #pragma unroll
    for (int i2 = 0; i2 < 8; i2++) { acc[i2][0] = 0.f; acc[i2][1] = 0.f; }

    for (int kc = 0; kc < 12; kc++) {
        __syncthreads();
        #pragma unroll
        for (int q = 0; q < 4; q++) {
            int i = q * 256 + t;
            int kkl = i >> 5, col = i & 31;
            int k = kc * 32 + kkl;
            sW[col][kkl] = __ldg(&Wv2[(k & 15) * 768 + (k >> 4) * 32 + col]);
        }
        #pragma unroll
        for (int q = 0; q < 16; q++) {
            int i = q * 256 + t;
            int node = i >> 5, kkl = i & 31;
            int n = base + node;
            sT[node][kkl] = (n < N_NODESC) ? g_T[(size_t)n * 384 + kc * 32 + kkl] : 0.f;
        }
        __syncthreads();
        #pragma unroll
        for (int kk4 = 0; kk4 < 8; kk4++) {
            float4 w0 = ((const float4*)sW[c0])[kk4];
            float4 w1 = ((const float4*)sW[c0 + 16])[kk4];
            #pragma unroll
            for (int i2 = 0; i2 < 8; i2++) {
                float4 tv = ((const float4*)sT[g * 8 + i2])[kk4];
                acc[i2][0] += tv.x * w0.x + tv.y * w0.y + tv.z * w0.z + tv.w * w0.w;
                acc[i2][1] += tv.x * w1.x + tv.y * w1.y + tv.z * w1.z + tv.w * w1.w;
            }
        }
    }
    #pragma unroll
    for (int i2 = 0; i2 < 8; i2++) {
        int n = base + g * 8 + i2;
        if (n < N_NODESC) {
            out[n * 32 + c0]      = acc[i2][0] * C_V;
            out[n * 32 + c0 + 16] = acc[i2][1] * C_V;
        }
    }
}

// ---------------- launch ----------------
extern "C" void kernel_launch(void* const* d_in, const int* in_sizes, int n_in,
                              void* d_out, int out_size) {
    (void)in_sizes; (void)n_in; (void)out_size;
    const float* x    = (const float*)d_in[0];
    const float* pos  = (const float*)d_in[1];
    const float* Wq   = (const float*)d_in[2];
    const float* Wk1  = (const float*)d_in[3];
    const float* Wk2  = (const float*)d_in[4];
    const float* Wv1  = (const float*)d_in[5];
    const float* Wv2  = (const float*)d_in[6];
    const float* Wdot = (const float*)d_in[7];
    const int* esrc   = (const int*)d_in[8];
    const int* edst   = (const int*)d_in[9];
    float* out = (float*)d_out;

    k_zeroprep<<<1 + (N_NODESC + 383) / 384, 384>>>(Wq, Wdot, Wk2);
    k_hist<<<(N_EDGESC + 255) / 256, 256>>>(edst);
    k_scan<<<1, 1024>>>();
    k_scatter<<<(N_EDGESC + 255) / 256, 256>>>(esrc, edst);
    k_R<<<N_NODESC / RT_NODES, 384>>>(x);
    k_edge<<<(N_NODESC + 7) / 8, 256>>>(x, pos, Wk1, Wv1);
    k_out<<<(N_NODESC + 127) / 128, 256>>>(Wv2, out);
}